// round 16
// baseline (speedup 1.0000x reference)
#include <cuda_runtime.h>
#include <cstdint>

#define HDIM 4096
#define VOCAB 50257
#define SEQL 2048
#define TOPK 50
#define MINKEEP 5
#define HSPLIT 4
#define HCHUNK (HDIM / HSPLIT)          // 1024
#define NVBLK ((VOCAB + 255) / 256)     // 197
#define CAP 4096
#define BMW ((VOCAB + 31) / 32)

__device__ float g_part[HSPLIT * VOCAB];
__device__ float g_logits[VOCAB];
__device__ unsigned int g_coarse[1024];
__device__ unsigned int g_bitmap[BMW];
__device__ int g_done[NVBLK];
__device__ unsigned int g_bm_ready;

__device__ __forceinline__ unsigned int fkey(float f) {
    unsigned int u = __float_as_uint(f);
    return (u & 0x80000000u) ? ~u : (u | 0x80000000u);
}

// ------- GEMV: per-block LN stats + inline LN + 16-in-flight stream (UNCHANGED from R15).
//         Block (0,0) builds penalty bitmap (+ready flag). 4th finisher per column-group
//         runs the combine+penalty+coarse-hist epilogue (overlapped with other SMs' streaming). -------
__global__ void __launch_bounds__(256, 6) gemv_kernel(const float* __restrict__ W,
                                                      const float* __restrict__ hin,
                                                      const float* __restrict__ gamma,
                                                      const float* __restrict__ beta,
                                                      const void* __restrict__ ids_raw,
                                                      const float* __restrict__ pen) {
    __shared__ float ws[8];
    __shared__ float sh_mu, sh_rstd;
    __shared__ float xs[HCHUNK];
    __shared__ int bad;
    __shared__ int sh_last;
    int tid = threadIdx.x;
    int lane = tid & 31, warp = tid >> 5;
    int hb = blockIdx.y;
    int h0 = hb * HCHUNK;

    // ---- per-block LN statistics over full H (deterministic fixed tree) ----
    float4 h4[4];
#pragma unroll
    for (int k = 0; k < 4; k++) h4[k] = ((const float4*)hin)[tid + k * 256];
    float s = 0.f;
#pragma unroll
    for (int k = 0; k < 4; k++) s += (h4[k].x + h4[k].y) + (h4[k].z + h4[k].w);
#pragma unroll
    for (int o = 16; o > 0; o >>= 1) s += __shfl_down_sync(0xffffffffu, s, o);
    if (lane == 0) ws[warp] = s;
    __syncthreads();
    if (tid == 0) {
        float t = ((ws[0] + ws[1]) + (ws[2] + ws[3])) + ((ws[4] + ws[5]) + (ws[6] + ws[7]));
        sh_mu = t / HDIM;
    }
    __syncthreads();
    float mu = sh_mu;
    float q = 0.f;
#pragma unroll
    for (int k = 0; k < 4; k++) {
        float dx = h4[k].x - mu, dy = h4[k].y - mu, dz = h4[k].z - mu, dw = h4[k].w - mu;
        q += (dx * dx + dy * dy) + (dz * dz + dw * dw);
    }
#pragma unroll
    for (int o = 16; o > 0; o >>= 1) q += __shfl_down_sync(0xffffffffu, q, o);
    if (lane == 0) ws[warp] = q;
    __syncthreads();
    if (tid == 0) {
        float t = ((ws[0] + ws[1]) + (ws[2] + ws[3])) + ((ws[4] + ws[5]) + (ws[6] + ws[7]));
        sh_rstd = rsqrtf(t / HDIM + 1e-5f);
    }
    __syncthreads();
    float rstd = sh_rstd;

    // ---- block (0,0): penalty bitmap (zero + int64/int32 detect + build) + ready flag ----
    if (blockIdx.x == 0 && hb == 0) {
        for (int i = tid; i < BMW; i += 256) g_bitmap[i] = 0u;
        if (tid == 0) bad = 0;
        __syncthreads();
        const long long* ll = (const long long*)ids_raw;
        int myBad = 0;
#pragma unroll
        for (int j = 0; j < 4; j++) {              // probe first 8KB only (safe both ways)
            long long p = ll[tid + j * 256];
            if (p < 0 || p >= VOCAB) myBad = 1;
        }
        if (myBad) atomicOr(&bad, 1);
        __syncthreads();
        int is64 = (bad == 0);
        if (is64) {
#pragma unroll
            for (int j = 0; j < 8; j++) {
                long long id = ll[tid + j * 256];
                atomicOr(&g_bitmap[(int)(id >> 5)], 1u << ((int)id & 31));
            }
        } else {
            const int* ii = (const int*)ids_raw;
#pragma unroll
            for (int j = 0; j < 8; j++) {
                int id = ii[tid + j * 256];
                atomicOr(&g_bitmap[id >> 5], 1u << (id & 31));
            }
        }
        __syncthreads();
        if (tid == 0) { __threadfence(); atomicExch(&g_bm_ready, 1u); }
    }

    // ---- stage LN'd chunk, then stream (UNCHANGED core) ----
    for (int i = tid; i < HCHUNK; i += 256)
        xs[i] = (hin[h0 + i] - mu) * rstd * gamma[h0 + i] + beta[h0 + i];
    __syncthreads();
    int v = blockIdx.x * 256 + tid;
    bool act = (v < VOCAB);
    if (act) {
        const float* wp = W + (size_t)h0 * VOCAB + v;
        float a0 = 0.f, a1 = 0.f, a2 = 0.f, a3 = 0.f;
        for (int i = 0; i < HCHUNK; i += 16) {
            float w[16];
#pragma unroll
            for (int j = 0; j < 16; j++) w[j] = __ldcs(wp + (size_t)j * VOCAB);
            wp += 16 * (size_t)VOCAB;
#pragma unroll
            for (int j = 0; j < 16; j += 4) {
                a0 += xs[i + j]     * w[j];
                a1 += xs[i + j + 1] * w[j + 1];
                a2 += xs[i + j + 2] * w[j + 2];
                a3 += xs[i + j + 3] * w[j + 3];
            }
        }
        g_part[hb * VOCAB + v] = (a0 + a1) + (a2 + a3);
    }

    // ---- 4th-finisher epilogue: combine + penalty + coarse hist (overlapped) ----
    __threadfence();
    __syncthreads();
    if (tid == 0) sh_last = (atomicAdd(&g_done[blockIdx.x], 1) == 3);
    __syncthreads();
    if (!sh_last) return;
    if (tid == 0) {
        while (atomicAdd(&g_bm_ready, 0u) == 0u) __nanosleep(32);
    }
    __syncthreads();
    __threadfence();
    if (act) {
        float r = (g_part[v] + g_part[VOCAB + v]) +
                  (g_part[2 * VOCAB + v] + g_part[3 * VOCAB + v]);
        if ((g_bitmap[v >> 5] >> (v & 31)) & 1u) {
            float p = pen[0];
            r = (r < 0.f) ? r * p : r / p;
        }
        g_logits[v] = r;
        atomicAdd(&g_coarse[fkey(r) >> 22], 1u);
    }
}

// ------- ONE tail kernel: threshold + MLP-batched collect + sort + sample + self-clean -------
#define SCANB 16
#define NBATCH ((VOCAB + 1024 * SCANB - 1) / (1024 * SCANB))   // 4

__global__ void __launch_bounds__(1024) tail_kernel(
        const float* __restrict__ tp_,
        const float* __restrict__ temp_,
        float* __restrict__ out, int out_size) {
    __shared__ unsigned cs[1024];
    __shared__ unsigned ws[32];
    __shared__ unsigned sh_Bf;
    __shared__ int cnt;
    __shared__ float cv[CAP];
    __shared__ int   ci[CAP];
    __shared__ float tv[TOPK];
    __shared__ int   tix[TOPK];
    __shared__ float sx[TOPK];
    __shared__ float sp[TOPK];
    int tid = threadIdx.x;

    // ---- threshold from coarse hist ----
    unsigned c = g_coarse[tid];
    cs[tid] = c;
    unsigned s = c;
    for (int o = 16; o > 0; o >>= 1) s += __shfl_down_sync(0xffffffffu, s, o);
    if ((tid & 31) == 0) ws[tid >> 5] = s;
    if (tid == 0) cnt = 0;
    __syncthreads();
    if (tid == 0) {
        unsigned acc = 0;
        int w = 31;
        for (; w > 0; --w) {
            if (acc + ws[w] >= (unsigned)TOPK) break;
            acc += ws[w];
        }
        int B = w * 32;
        for (int b = w * 32 + 31; b >= w * 32; --b) {
            unsigned cc = cs[b];
            if (acc + cc >= (unsigned)TOPK) { B = b; break; }
            acc += cc;
        }
        sh_Bf = (unsigned)B << 22;
    }
    __syncthreads();
    unsigned Bf = sh_Bf;

    // ---- collect: 16 independent loads in flight per thread, then test/append ----
#pragma unroll
    for (int b = 0; b < NBATCH; b++) {
        float f[SCANB];
        int base = b * 1024 * SCANB + tid;
#pragma unroll
        for (int k = 0; k < SCANB; k++) {
            int v = base + k * 1024;
            f[k] = (v < VOCAB) ? __ldcs(&g_logits[v]) : -1e30f;
        }
#pragma unroll
        for (int k = 0; k < SCANB; k++) {
            int v = base + k * 1024;
            if (v < VOCAB && fkey(f[k]) >= Bf) {
                int p = atomicAdd(&cnt, 1);
                if (p < CAP) { cv[p] = f[k]; ci[p] = v; }
            }
        }
    }
    __syncthreads();

    // ---- rank-sort + sample ----
    int n = min(cnt, CAP);
    for (int i = tid; i < n; i += 1024) {
        float v = cv[i]; int ix = ci[i];
        int r = 0;
        for (int j = 0; j < n; j++) {
            float vj = cv[j];
            if (vj > v || (vj == v && ci[j] < ix)) r++;
        }
        if (r < TOPK) { tv[r] = v; tix[r] = ix; }
    }
    __syncthreads();
    if (tid < TOPK) sx[tid] = tv[tid] / temp_[0];
    __syncthreads();
    if (tid < TOPK) sp[tid] = expf(sx[tid] - sx[0]);
    __syncthreads();
    if (tid == 0) {
        float tp = tp_[0];
        float m = sx[0];
        float ssum = 0.f;
        for (int i = 0; i < TOPK; i++) ssum += sp[i];
        float cum = 0.f, s2 = 0.f;
        for (int i = 0; i < TOPK; i++) {
            cum += sp[i] / ssum;
            bool keep = (cum < tp) || (i < MINKEEP);
            float f = keep ? sx[i] : -1000.0f;
            float e = expf(f - m);
            sp[i] = e;
            s2 += e;
        }
        sx[0] = s2;
    }
    __syncthreads();
    if (tid < TOPK) out[tid] = sp[tid] / sx[0];
    if (out_size >= 2 * TOPK && tid < TOPK) out[TOPK + tid] = (float)tix[tid];

    // ---- self-clean for next replay ----
    __syncthreads();
    g_coarse[tid] = 0u;
    for (int i = tid; i < NVBLK; i += 1024) g_done[i] = 0;
    if (tid == 0) g_bm_ready = 0u;
}

extern "C" void kernel_launch(void* const* d_in, const int* in_sizes, int n_in,
                              void* d_out, int out_size) {
    const float* hidden = (const float*)d_in[0];
    const void*  ids    = d_in[1];
    const float* top_p  = (const float*)d_in[2];
    const float* temp   = (const float*)d_in[3];
    const float* pen    = (const float*)d_in[4];
    const float* gamma  = (const float*)d_in[5];
    const float* beta   = (const float*)d_in[6];
    const float* W      = (const float*)d_in[7];
    float* out = (float*)d_out;

    dim3 g(NVBLK, HSPLIT);
    gemv_kernel<<<g, 256>>>(W, hidden, gamma, beta, ids, pen);
    tail_kernel<<<1, 1024>>>(top_p, temp, out, out_size);
}

// round 17
// speedup vs baseline: 1.0071x; 1.0071x over previous
#include <cuda_runtime.h>
#include <cstdint>

#define HDIM 4096
#define VOCAB 50257
#define SEQL 2048
#define TOPK 50
#define MINKEEP 5
#define HSPLIT 4
#define HCHUNK (HDIM / HSPLIT)          // 1024
#define NVBLK ((VOCAB + 255) / 256)     // 197
#define CAP 4096
#define BMW ((VOCAB + 31) / 32)

__device__ float g_part[HSPLIT * VOCAB];
__device__ float g_logits[VOCAB];
__device__ unsigned int g_coarse[1024];
__device__ unsigned int g_bitmap[BMW];
__device__ int g_done[NVBLK];
__device__ unsigned int g_bm_ready;

__device__ __forceinline__ unsigned int fkey(float f) {
    unsigned int u = __float_as_uint(f);
    return (u & 0x80000000u) ? ~u : (u | 0x80000000u);
}

// ------- GEMV: per-block LN stats + inline LN + 16-in-flight stream (UNCHANGED from R15).
//         Block (0,0) builds penalty bitmap (+ready flag). 4th finisher per column-group
//         runs the combine+penalty+coarse-hist epilogue (overlapped with other SMs' streaming). -------
__global__ void __launch_bounds__(256, 6) gemv_kernel(const float* __restrict__ W,
                                                      const float* __restrict__ hin,
                                                      const float* __restrict__ gamma,
                                                      const float* __restrict__ beta,
                                                      const void* __restrict__ ids_raw,
                                                      const float* __restrict__ pen) {
    __shared__ float ws[8];
    __shared__ float sh_mu, sh_rstd;
    __shared__ float xs[HCHUNK];
    __shared__ int bad;
    __shared__ int sh_last;
    int tid = threadIdx.x;
    int lane = tid & 31, warp = tid >> 5;
    int hb = blockIdx.y;
    int h0 = hb * HCHUNK;

    // ---- per-block LN statistics over full H (deterministic fixed tree) ----
    float4 h4[4];
#pragma unroll
    for (int k = 0; k < 4; k++) h4[k] = ((const float4*)hin)[tid + k * 256];
    float s = 0.f;
#pragma unroll
    for (int k = 0; k < 4; k++) s += (h4[k].x + h4[k].y) + (h4[k].z + h4[k].w);
#pragma unroll
    for (int o = 16; o > 0; o >>= 1) s += __shfl_down_sync(0xffffffffu, s, o);
    if (lane == 0) ws[warp] = s;
    __syncthreads();
    if (tid == 0) {
        float t = ((ws[0] + ws[1]) + (ws[2] + ws[3])) + ((ws[4] + ws[5]) + (ws[6] + ws[7]));
        sh_mu = t / HDIM;
    }
    __syncthreads();
    float mu = sh_mu;
    float q = 0.f;
#pragma unroll
    for (int k = 0; k < 4; k++) {
        float dx = h4[k].x - mu, dy = h4[k].y - mu, dz = h4[k].z - mu, dw = h4[k].w - mu;
        q += (dx * dx + dy * dy) + (dz * dz + dw * dw);
    }
#pragma unroll
    for (int o = 16; o > 0; o >>= 1) q += __shfl_down_sync(0xffffffffu, q, o);
    if (lane == 0) ws[warp] = q;
    __syncthreads();
    if (tid == 0) {
        float t = ((ws[0] + ws[1]) + (ws[2] + ws[3])) + ((ws[4] + ws[5]) + (ws[6] + ws[7]));
        sh_rstd = rsqrtf(t / HDIM + 1e-5f);
    }
    __syncthreads();
    float rstd = sh_rstd;

    // ---- block (0,0): penalty bitmap (zero + int64/int32 detect + build) + ready flag ----
    if (blockIdx.x == 0 && hb == 0) {
        for (int i = tid; i < BMW; i += 256) g_bitmap[i] = 0u;
        if (tid == 0) bad = 0;
        __syncthreads();
        const long long* ll = (const long long*)ids_raw;
        int myBad = 0;
#pragma unroll
        for (int j = 0; j < 4; j++) {              // probe first 8KB only (safe both ways)
            long long p = ll[tid + j * 256];
            if (p < 0 || p >= VOCAB) myBad = 1;
        }
        if (myBad) atomicOr(&bad, 1);
        __syncthreads();
        int is64 = (bad == 0);
        if (is64) {
#pragma unroll
            for (int j = 0; j < 8; j++) {
                long long id = ll[tid + j * 256];
                atomicOr(&g_bitmap[(int)(id >> 5)], 1u << ((int)id & 31));
            }
        } else {
            const int* ii = (const int*)ids_raw;
#pragma unroll
            for (int j = 0; j < 8; j++) {
                int id = ii[tid + j * 256];
                atomicOr(&g_bitmap[id >> 5], 1u << (id & 31));
            }
        }
        __syncthreads();
        if (tid == 0) { __threadfence(); atomicExch(&g_bm_ready, 1u); }
    }

    // ---- stage LN'd chunk, then stream (UNCHANGED core) ----
    for (int i = tid; i < HCHUNK; i += 256)
        xs[i] = (hin[h0 + i] - mu) * rstd * gamma[h0 + i] + beta[h0 + i];
    __syncthreads();
    int v = blockIdx.x * 256 + tid;
    bool act = (v < VOCAB);
    if (act) {
        const float* wp = W + (size_t)h0 * VOCAB + v;
        float a0 = 0.f, a1 = 0.f, a2 = 0.f, a3 = 0.f;
        for (int i = 0; i < HCHUNK; i += 16) {
            float w[16];
#pragma unroll
            for (int j = 0; j < 16; j++) w[j] = __ldcs(wp + (size_t)j * VOCAB);
            wp += 16 * (size_t)VOCAB;
#pragma unroll
            for (int j = 0; j < 16; j += 4) {
                a0 += xs[i + j]     * w[j];
                a1 += xs[i + j + 1] * w[j + 1];
                a2 += xs[i + j + 2] * w[j + 2];
                a3 += xs[i + j + 3] * w[j + 3];
            }
        }
        g_part[hb * VOCAB + v] = (a0 + a1) + (a2 + a3);
    }

    // ---- 4th-finisher epilogue: combine + penalty + coarse hist (overlapped) ----
    __threadfence();
    __syncthreads();
    if (tid == 0) sh_last = (atomicAdd(&g_done[blockIdx.x], 1) == 3);
    __syncthreads();
    if (!sh_last) return;
    if (tid == 0) {
        while (atomicAdd(&g_bm_ready, 0u) == 0u) __nanosleep(32);
    }
    __syncthreads();
    __threadfence();
    if (act) {
        float r = (g_part[v] + g_part[VOCAB + v]) +
                  (g_part[2 * VOCAB + v] + g_part[3 * VOCAB + v]);
        if ((g_bitmap[v >> 5] >> (v & 31)) & 1u) {
            float p = pen[0];
            r = (r < 0.f) ? r * p : r / p;
        }
        g_logits[v] = r;
        atomicAdd(&g_coarse[fkey(r) >> 22], 1u);
    }
}

// ------- ONE tail kernel: suffix-scan threshold + pipelined collect + sort + sample -------
#define SCANB 16
#define NBATCH ((VOCAB + 1024 * SCANB - 1) / (1024 * SCANB))   // 4

__global__ void __launch_bounds__(1024) tail_kernel(
        const float* __restrict__ tp_,
        const float* __restrict__ temp_,
        float* __restrict__ out, int out_size) {
    __shared__ unsigned sa[1024];
    __shared__ unsigned sb[1024];
    __shared__ unsigned sh_Bf;
    __shared__ int cnt;
    __shared__ float cv[CAP];
    __shared__ int   ci[CAP];
    __shared__ float tv[TOPK];
    __shared__ int   tix[TOPK];
    __shared__ float sx[TOPK];
    __shared__ float sp[TOPK];
    int tid = threadIdx.x;

    // ---- prefetch collect batch 0 (independent of threshold) ----
    float f0[SCANB];
#pragma unroll
    for (int k = 0; k < SCANB; k++) {
        int v = tid + k * 1024;
        f0[k] = (v < VOCAB) ? __ldcs(&g_logits[v]) : -1e30f;
    }

    // ---- parallel suffix-sum threshold over coarse hist ----
    sa[tid] = g_coarse[tid];
    if (tid == 0) cnt = 0;
    __syncthreads();
    // Hillis-Steele suffix scan, ping-pong sa<->sb (10 steps)
#pragma unroll
    for (int step = 1; step < 1024; step <<= 1) {
        unsigned* src = (step & 0x2AAu) ? sb : sa;   // odd-numbered steps read sb
        unsigned* dst = (step & 0x2AAu) ? sa : sb;
        unsigned val = src[tid] + ((tid + step < 1024) ? src[tid + step] : 0u);
        __syncthreads();
        dst[tid] = val;
        __syncthreads();
    }
    // after 10 steps result is in sb (last write: step=512 -> dst = sb? verify parity: steps 1,2,4,...,512
    // mask 0x2AA = bits 1,3,5,7,9 -> steps 2,8,32,128,512 write sa; steps 1,4,16,64,256 write sb.
    // Last step 512 (bit 9 set) writes sa.
    unsigned* suf = sa;
    if (suf[tid] >= (unsigned)TOPK && (tid == 1023 || suf[tid + 1] < (unsigned)TOPK))
        sh_Bf = (unsigned)tid << 22;
    __syncthreads();
    unsigned Bf = sh_Bf;

    // ---- pipelined collect: test batch b while loading batch b+1 ----
    float f1[SCANB];
#pragma unroll
    for (int b = 0; b < NBATCH; b++) {
        if (b + 1 < NBATCH) {
            int nb = (b + 1) * 1024 * SCANB + tid;
#pragma unroll
            for (int k = 0; k < SCANB; k++) {
                int v = nb + k * 1024;
                f1[k] = (v < VOCAB) ? __ldcs(&g_logits[v]) : -1e30f;
            }
        }
        int base = b * 1024 * SCANB + tid;
#pragma unroll
        for (int k = 0; k < SCANB; k++) {
            int v = base + k * 1024;
            if (v < VOCAB && fkey(f0[k]) >= Bf) {
                int p = atomicAdd(&cnt, 1);
                if (p < CAP) { cv[p] = f0[k]; ci[p] = v; }
            }
        }
#pragma unroll
        for (int k = 0; k < SCANB; k++) f0[k] = f1[k];
    }
    __syncthreads();

    // ---- rank-sort ----
    int n = min(cnt, CAP);
    for (int i = tid; i < n; i += 1024) {
        float v = cv[i]; int ix = ci[i];
        int r = 0;
        for (int j = 0; j < n; j++) {
            float vj = cv[j];
            if (vj > v || (vj == v && ci[j] < ix)) r++;
        }
        if (r < TOPK) { tv[r] = v; tix[r] = ix; }
    }
    __syncthreads();
    if (tid < TOPK) sx[tid] = tv[tid] / temp_[0];
    __syncthreads();
    if (tid < TOPK) sp[tid] = expf(sx[tid] - sx[0]);
    __syncthreads();
    if (tid == 0) {
        // masked entries: expf(-1000 - m) == 0.0f exactly, so q[i] = keep ? sp[i] : 0
        float tp = tp_[0];
        float ssum = 0.f;
        for (int i = 0; i < TOPK; i++) ssum += sp[i];
        float cum = 0.f, s2 = 0.f;
        for (int i = 0; i < TOPK; i++) {
            cum += sp[i] / ssum;
            bool keep = (cum < tp) || (i < MINKEEP);
            float e = keep ? sp[i] : 0.0f;
            sp[i] = e;
            s2 += e;
        }
        sx[0] = s2;
    }
    __syncthreads();
    if (tid < TOPK) out[tid] = sp[tid] / sx[0];
    if (out_size >= 2 * TOPK && tid < TOPK) out[TOPK + tid] = (float)tix[tid];

    // ---- self-clean for next replay ----
    __syncthreads();
    g_coarse[tid] = 0u;
    for (int i = tid; i < NVBLK; i += 1024) g_done[i] = 0;
    if (tid == 0) g_bm_ready = 0u;
}

extern "C" void kernel_launch(void* const* d_in, const int* in_sizes, int n_in,
                              void* d_out, int out_size) {
    const float* hidden = (const float*)d_in[0];
    const void*  ids    = d_in[1];
    const float* top_p  = (const float*)d_in[2];
    const float* temp   = (const float*)d_in[3];
    const float* pen    = (const float*)d_in[4];
    const float* gamma  = (const float*)d_in[5];
    const float* beta   = (const float*)d_in[6];
    const float* W      = (const float*)d_in[7];
    float* out = (float*)d_out;

    dim3 g(NVBLK, HSPLIT);
    gemv_kernel<<<g, 256>>>(W, hidden, gamma, beta, ids, pen);
    tail_kernel<<<1, 1024>>>(top_p, temp, out, out_size);
}